// round 17
// baseline (speedup 1.0000x reference)
#include <cuda_runtime.h>
#include <cuda_fp16.h>
#include <cstdint>

#define EPS_F 1e-15f

static const int N_GCN  = 8192;
static const int DIN_   = 256;
static const int DOUT_  = 256;

// ---------------------------------------------------------------------------
// Scratch (__device__ globals; no cudaMalloc allowed)
// ---------------------------------------------------------------------------
__device__ float g_d[8192];
__device__ __align__(16) float  g_g[8192 * 256];            // g = d*(x@W^T) fp32, [m][n]
__device__ __align__(16) __half g_gT_h[256 * 8192];         // gT hi fp16, [n][k]
__device__ __align__(16) __half g_Ah[(size_t)8192 * 8192];  // A as fp16, [m][k]

// ---------------------------------------------------------------------------
// PTX helpers (plain sm_103-legal: ldmatrix / mma.sync / cp.async)
// ---------------------------------------------------------------------------
__device__ __forceinline__ uint32_t smem_to_u32(const void* p) {
    uint32_t a;
    asm("{ .reg .u64 t; cvta.to.shared.u64 t, %1; cvt.u32.u64 %0, t; }" : "=r"(a) : "l"(p));
    return a;
}

#define LDMX4(R, addr) \
    asm volatile("ldmatrix.sync.aligned.m8n8.x4.shared.b16 {%0,%1,%2,%3}, [%4];" \
        : "=r"((R)[0]), "=r"((R)[1]), "=r"((R)[2]), "=r"((R)[3]) : "r"(addr))

#define MMA16816(d, a, b0, b1) \
    asm volatile("mma.sync.aligned.m16n8k16.row.col.f32.f16.f16.f32 " \
        "{%0,%1,%2,%3}, {%4,%5,%6,%7}, {%8,%9}, {%0,%1,%2,%3};" \
        : "+f"((d)[0]), "+f"((d)[1]), "+f"((d)[2]), "+f"((d)[3]) \
        : "r"((a)[0]), "r"((a)[1]), "r"((a)[2]), "r"((a)[3]), "r"(b0), "r"(b1))

#define CP_ASYNC16(dst, src) \
    asm volatile("cp.async.cg.shared.global [%0], [%1], 16;" :: "r"(dst), "l"(src) : "memory")
#define CP_COMMIT() asm volatile("cp.async.commit_group;" ::: "memory")
#define CP_WAIT1()  asm volatile("cp.async.wait_group 1;" ::: "memory")

__device__ __forceinline__ uint32_t h2u(__half2 v) { return *reinterpret_cast<uint32_t*>(&v); }

// ---------------------------------------------------------------------------
// Kernel A: degrees + write A as fp16 (Ah) for the async GEMM A-path.
// ---------------------------------------------------------------------------
__global__ void deg_kernel(const float* __restrict__ A, int N) {
    int row = blockIdx.x;
    const float4* Ar = (const float4*)(A + (size_t)row * N);
    __half* Ah = g_Ah + (size_t)row * N;
    int n4 = N >> 2;
    float s = 0.0f;
    for (int j = threadIdx.x; j < n4; j += blockDim.x) {
        float4 v = Ar[j];
        s += (v.x > EPS_F ? 1.0f : 0.0f);
        s += (v.y > EPS_F ? 1.0f : 0.0f);
        s += (v.z > EPS_F ? 1.0f : 0.0f);
        s += (v.w > EPS_F ? 1.0f : 0.0f);
        __half2 h0 = __floats2half2_rn(v.x, v.y);
        __half2 h1 = __floats2half2_rn(v.z, v.w);
        *(uint2*)(Ah + j * 4) = make_uint2(h2u(h0), h2u(h1));
    }
    __shared__ float red[256];
    red[threadIdx.x] = s;
    __syncthreads();
    for (int off = 128; off > 0; off >>= 1) {
        if (threadIdx.x < off) red[threadIdx.x] += red[threadIdx.x + off];
        __syncthreads();
    }
    if (threadIdx.x == 0) g_d[row] = rsqrtf(1.0f + red[0]);
}

// ---------------------------------------------------------------------------
// Kernel B: g = d*(x@W^T) fp32 + transposed fp16 hi split (proven)
// ---------------------------------------------------------------------------
__global__ void xw_kernel(const float* __restrict__ x,
                          const float* __restrict__ W) {
    __shared__ float xs[16][68];
    __shared__ float ws[16][68];

    int bm = blockIdx.x * 64;
    int bn = blockIdx.y * 64;
    int tid = threadIdx.x;
    int tx = tid & 15;
    int ty = tid >> 4;

    float acc[4][4];
#pragma unroll
    for (int i = 0; i < 4; i++)
#pragma unroll
        for (int j = 0; j < 4; j++) acc[i][j] = 0.0f;

    for (int kt = 0; kt < DIN_; kt += 16) {
        {
            int r = tid >> 2, c = tid & 3;
            float4 v = *(const float4*)(x + (size_t)(bm + r) * DIN_ + kt + c * 4);
            xs[c * 4 + 0][r] = v.x; xs[c * 4 + 1][r] = v.y;
            xs[c * 4 + 2][r] = v.z; xs[c * 4 + 3][r] = v.w;
        }
        {
            int r = tid >> 2, c = tid & 3;
            float4 v = *(const float4*)(W + (size_t)(bn + r) * DIN_ + kt + c * 4);
            ws[c * 4 + 0][r] = v.x; ws[c * 4 + 1][r] = v.y;
            ws[c * 4 + 2][r] = v.z; ws[c * 4 + 3][r] = v.w;
        }
        __syncthreads();
#pragma unroll
        for (int k = 0; k < 16; k++) {
            float4 a = *(const float4*)&xs[k][ty * 4];
            float4 b = *(const float4*)&ws[k][tx * 4];
            float av[4] = {a.x, a.y, a.z, a.w};
            float bv[4] = {b.x, b.y, b.z, b.w};
#pragma unroll
            for (int i = 0; i < 4; i++)
#pragma unroll
                for (int j = 0; j < 4; j++) acc[i][j] += av[i] * bv[j];
        }
        __syncthreads();
    }

    int m0 = bm + ty * 4;
    float dm[4];
#pragma unroll
    for (int i = 0; i < 4; i++) dm[i] = g_d[m0 + i];

#pragma unroll
    for (int j = 0; j < 4; j++) {
        int n = bn + tx * 4 + j;
        float gv[4];
#pragma unroll
        for (int i = 0; i < 4; i++) {
            gv[i] = dm[i] * acc[i][j];
            g_g[(size_t)(m0 + i) * DOUT_ + n] = gv[i];
        }
        __half2 h01 = __floats2half2_rn(gv[0], gv[1]);
        __half2 h23 = __floats2half2_rn(gv[2], gv[3]);
        *(uint2*)(&g_gT_h[(size_t)n * N_GCN + m0]) = make_uint2(h2u(h01), h2u(h23));
    }
}

// ---------------------------------------------------------------------------
// Kernel C: warp-MMA GEMM, fully-async, BK=64. out = relu(d*(Ah@gh+g)) + copy.
// CTA 128x128, BK=64, 16 warps (4M x 4N), warp tile 32x32, 128 chunks.
// Both tiles cp.async from fp16 scratch, 3-stage pipeline (wait_group<=1).
// BK=64 is now safe: no LDG->cvt->STS register staging (that was R7/R12's
// failure mode) -- per-chunk fixed cost paid half as often.
// ---------------------------------------------------------------------------
static const int BM = 128, BN = 128, BK = 64;
static const int TSTRIDE = 144;                 // 64 fp16 = 128B + 16B pad
static const int TILE_B  = 128 * TSTRIDE;       // 18432 B
static const int BUF_B   = 2 * TILE_B;          // Ah, Bh = 36864 B per stage
static const int STAGES  = 3;
static const int SMEM_TOTAL_C = STAGES * BUF_B; // 110592 B (dynamic)

__global__ void __launch_bounds__(512, 1)
agemm_mma(const float* __restrict__ A, float* __restrict__ out,
          float* __restrict__ Acopy, int doCopy, int K) {
    extern __shared__ char smem[];
    uint32_t sbase = smem_to_u32(smem);

    int tid  = threadIdx.x;
    int lane = tid & 31;
    int wid  = tid >> 5;
    int wm = wid & 3;                  // 0..3 -> 32-row block
    int wn = wid >> 2;                 // 0..3 -> 32-col block
    int bm = blockIdx.x * BM;
    int by = blockIdx.y;
    int bn = by * BN;

    // async loaders: tile 128 rows x 64 fp16 = 1024 x 16B segs; 2/thread
    int r0l = tid >> 3, s0l = tid & 7;             // first seg
    int r1l = (tid + 512) >> 3, s1l = s0l;         // second seg (rows 64..127)
    const __half* Ah0 = g_Ah + (size_t)(bm + r0l) * K + s0l * 8;
    const __half* Ah1 = g_Ah + (size_t)(bm + r1l) * K + s1l * 8;
    const __half* Bh0 = g_gT_h + (size_t)(bn + r0l) * K + s0l * 8;
    const __half* Bh1 = g_gT_h + (size_t)(bn + r1l) * K + s1l * 8;
    uint32_t d0 = (uint32_t)r0l * TSTRIDE + s0l * 16;
    uint32_t d1 = (uint32_t)r1l * TSTRIDE + s1l * 16;

    // copy stream (fp32): each thread owns 16 floats of one row per chunk
    int crow = tid >> 2;
    int cq   = tid & 3;
    const float* Aptr = A + (size_t)(bm + crow) * K + cq * 16;
    float* Cptr = Acopy ? (Acopy + (size_t)(bm + crow) * K + cq * 16) : (float*)0;

    uint32_t aoff0 = (uint32_t)(wm * 32 + (lane & 15)) * TSTRIDE + (lane >> 4) * 16;
    uint32_t brow  = (lane & 7) + ((lane >> 4) & 1) * 8;
    uint32_t boff0 = (uint32_t)(wn * 32 + brow) * TSTRIDE + ((lane >> 3) & 1) * 16;

    float acc[2][4][4];
#pragma unroll
    for (int f = 0; f < 2; f++)
#pragma unroll
        for (int n = 0; n < 4; n++)
#pragma unroll
            for (int e = 0; e < 4; e++) acc[f][n][e] = 0.0f;

    const int NC = K / BK;    // 128

    auto issue_chunk = [&](int stage, int kt) {
        uint32_t base = sbase + stage * BUF_B;
        CP_ASYNC16(base + d0, Ah0 + kt);
        CP_ASYNC16(base + d1, Ah1 + kt);
        CP_ASYNC16(base + TILE_B + d0, Bh0 + kt);
        CP_ASYNC16(base + TILE_B + d1, Bh1 + kt);
    };

    // ---- prologue: chunks 0,1 -> stages 0,1 ----
    issue_chunk(0, 0);
    CP_COMMIT();
    issue_chunk(1, BK);
    CP_COMMIT();

    for (int i = 0; i < NC; i++) {
        CP_WAIT1();            // chunk i complete (<=1 group pending)
        __syncthreads();       // all warps past chunk i-1 MMAs -> stage reuse safe

        if (i + 2 < NC) issue_chunk((i + 2) % STAGES, (i + 2) * BK);
        CP_COMMIT();

        // copy stream: LDG now (latency hides under MMAs), STG after
        float4 v[4];
        bool own = doCopy && ((i >> 6) == by);
        if (own) {
            const float* Ap = Aptr + (size_t)i * BK;
#pragma unroll
            for (int q = 0; q < 4; q++) v[q] = *(const float4*)(Ap + q * 4);
        }

        uint32_t sa = sbase + (i % STAGES) * BUF_B;
        uint32_t sb = sa + TILE_B;

#pragma unroll
        for (int kh = 0; kh < 4; kh++) {
            uint32_t ah[2][4], bh[2][4];
            uint32_t ka = aoff0 + kh * 32;
            uint32_t kb = boff0 + kh * 32;
#pragma unroll
            for (int f = 0; f < 2; f++) LDMX4(ah[f], sa + ka + f * (16 * TSTRIDE));
#pragma unroll
            for (int p = 0; p < 2; p++) LDMX4(bh[p], sb + kb + p * (16 * TSTRIDE));

#pragma unroll
            for (int f = 0; f < 2; f++)
#pragma unroll
                for (int nf = 0; nf < 4; nf++) {
                    int p = nf >> 1, o = (nf & 1) * 2;
                    MMA16816(acc[f][nf], ah[f], bh[p][o], bh[p][o + 1]);
                }
        }

        if (own) {
            float* cp = Cptr + (size_t)i * BK;
#pragma unroll
            for (int q = 0; q < 4; q++) *(float4*)(cp + q * 4) = v[q];
        }
    }

    // ---- epilogue: out = relu(d * (acc + g)) ----
    int r0 = bm + wm * 32 + (lane >> 2);
    int c0 = bn + wn * 32 + (lane & 3) * 2;
#pragma unroll
    for (int f = 0; f < 2; f++) {
        int m1 = r0 + f * 16;
        int m2 = m1 + 8;
        float d1f = g_d[m1];
        float d2f = g_d[m2];
#pragma unroll
        for (int nf = 0; nf < 4; nf++) {
            int c = c0 + nf * 8;
            float2 g1 = *(const float2*)&g_g[(size_t)m1 * DOUT_ + c];
            float2 g2 = *(const float2*)&g_g[(size_t)m2 * DOUT_ + c];
            float2 o1, o2;
            o1.x = fmaxf(d1f * (acc[f][nf][0] + g1.x), 0.0f);
            o1.y = fmaxf(d1f * (acc[f][nf][1] + g1.y), 0.0f);
            o2.x = fmaxf(d2f * (acc[f][nf][2] + g2.x), 0.0f);
            o2.y = fmaxf(d2f * (acc[f][nf][3] + g2.y), 0.0f);
            *(float2*)&out[(size_t)m1 * DOUT_ + c] = o1;
            *(float2*)&out[(size_t)m2 * DOUT_ + c] = o2;
        }
    }
}

// ---------------------------------------------------------------------------
extern "C" void kernel_launch(void* const* d_in, const int* in_sizes, int n_in,
                              void* d_out, int out_size) {
    const float* x = (const float*)d_in[0];   // [8192, 256]
    const float* A = (const float*)d_in[1];   // [8192, 8192]
    const float* W = (const float*)d_in[2];   // [256, 256]
    float* out = (float*)d_out;

    const int N = N_GCN;
    const size_t out_elems = (size_t)N * DOUT_;

    int doCopy = ((size_t)out_size >= out_elems + (size_t)N * N) ? 1 : 0;
    float* Acopy = doCopy ? (out + out_elems) : (float*)0;

    cudaFuncSetAttribute(agemm_mma, cudaFuncAttributeMaxDynamicSharedMemorySize,
                         SMEM_TOTAL_C);

    // 1. degrees + Ah fp16 conversion
    deg_kernel<<<N, 256>>>(A, N);

    // 2. g = diag(d)*(x@W^T) fp32 + fp16 hi transposed split
    dim3 gridB(N / 64, DOUT_ / 64);
    xw_kernel<<<gridB, 256>>>(x, W);

    // 3. out = relu(diag(d)*(A@g + g)); async 3-stage BK=64 fp16 GEMM + copy
    dim3 gridC(N / BM, DOUT_ / BN);
    agemm_mma<<<gridC, 512, SMEM_TOTAL_C>>>(A, out, Acopy, doCopy, N);
}